// round 1
// baseline (speedup 1.0000x reference)
#include <cuda_runtime.h>
#include <math.h>

#define BATCH 8
#define CHN 192
#define CH3 576
#define IMH 128
#define IMW 128
#define NPIX (IMH*IMW)         // 16384
#define NHEADS 4
#define HDIM 48
#define NORI 9
#define NSPLIT 32
#define SPLITLEN (NPIX/NSPLIT) // 512
#define PI_F 3.14159265358979323846f

// ---- device scratch (no allocation allowed) ----
__device__ float g_qkv  [BATCH*CH3*NPIX];
__device__ float g_qkvdw[BATCH*CH3*NPIX];
__device__ float g_hogw [BATCH*NORI*NPIX];
__device__ float g_norms[2*BATCH*CHN];
__device__ float g_attnp[BATCH*NHEADS*NSPLIT*HDIM*HDIM];
__device__ float g_attn [BATCH*NHEADS*HDIM*HDIM];
__device__ float g_wf   [BATCH*CHN*CHN];

// ============================================================
// GEMM: C[z] (MxN) = A[z] (MxK, row-major lda=K) * B[z] (KxN, ldb=N)
// Tile 64x128, BK=8, thread tile 4x8, 256 threads.
// M = gridDim.y*64 (must divide), N divides 128, K divides 8.
// ============================================================
__global__ __launch_bounds__(256)
void gemm_kernel(const float* __restrict__ A, long sA,
                 const float* __restrict__ B, long sB,
                 float* __restrict__ Cm, long sC,
                 int N, int K)
{
    __shared__ float As[8][64];
    __shared__ float Bs[8][128];
    const float* Ab = A + (long)blockIdx.z * sA;
    const float* Bb = B + (long)blockIdx.z * sB;
    float*       Cb = Cm + (long)blockIdx.z * sC;
    const int m0 = blockIdx.y * 64;
    const int n0 = blockIdx.x * 128;
    const int t  = threadIdx.x;
    const int ty = t >> 4;     // 0..15
    const int tx = t & 15;     // 0..15

    float acc[4][8];
#pragma unroll
    for (int i = 0; i < 4; i++)
#pragma unroll
        for (int j = 0; j < 8; j++) acc[i][j] = 0.f;

    for (int k0 = 0; k0 < K; k0 += 8) {
        if (t < 128) {
            int row = t >> 1;
            int kq  = (t & 1) * 4;
            float4 v = *(const float4*)(Ab + (long)(m0 + row) * K + k0 + kq);
            As[kq+0][row] = v.x; As[kq+1][row] = v.y;
            As[kq+2][row] = v.z; As[kq+3][row] = v.w;
        }
        {
            int row = t >> 5;          // 0..7
            int col = (t & 31) * 4;    // 0..124
            *(float4*)&Bs[row][col] =
                *(const float4*)(Bb + (long)(k0 + row) * N + n0 + col);
        }
        __syncthreads();
#pragma unroll
        for (int kk = 0; kk < 8; kk++) {
            float4 a  = *(const float4*)&As[kk][ty * 4];
            float4 b0 = *(const float4*)&Bs[kk][tx * 8];
            float4 b1 = *(const float4*)&Bs[kk][tx * 8 + 4];
            float av[4] = {a.x, a.y, a.z, a.w};
            float bv[8] = {b0.x, b0.y, b0.z, b0.w, b1.x, b1.y, b1.z, b1.w};
#pragma unroll
            for (int i = 0; i < 4; i++)
#pragma unroll
                for (int j = 0; j < 8; j++)
                    acc[i][j] += av[i] * bv[j];
        }
        __syncthreads();
    }
#pragma unroll
    for (int i = 0; i < 4; i++) {
        float4 o0 = make_float4(acc[i][0], acc[i][1], acc[i][2], acc[i][3]);
        float4 o1 = make_float4(acc[i][4], acc[i][5], acc[i][6], acc[i][7]);
        float* dst = Cb + (long)(m0 + ty * 4 + i) * N + n0 + tx * 8;
        *(float4*)dst       = o0;
        *(float4*)(dst + 4) = o1;
    }
}

// ============================================================
// Sobel (replicate pad, kornia /8 kernels) -> channel-mean mag/ang
// -> per-pixel 9 HOG bin weights * mag into g_hogw.
// grid (IMH, BATCH), block 128 (one thread per w).
// ============================================================
__global__ __launch_bounds__(128)
void sobel_hog_kernel(const float* __restrict__ x)
{
    const int w = threadIdx.x;
    const int h = blockIdx.x;
    const int b = blockIdx.y;
    const int hm = h > 0 ? h - 1 : 0;
    const int hp = h < IMH - 1 ? h + 1 : IMH - 1;
    const int wm = w > 0 ? w - 1 : 0;
    const int wp = w < IMW - 1 ? w + 1 : IMW - 1;
    const float* xb = x + (long)b * CHN * NPIX;

    float msum = 0.f, asum = 0.f;
    for (int c = 0; c < CHN; c++) {
        const float* p = xb + (long)c * NPIX;
        float a00 = __ldg(p + hm*IMW + wm), a01 = __ldg(p + hm*IMW + w), a02 = __ldg(p + hm*IMW + wp);
        float a10 = __ldg(p + h *IMW + wm),                              a12 = __ldg(p + h *IMW + wp);
        float a20 = __ldg(p + hp*IMW + wm), a21 = __ldg(p + hp*IMW + w), a22 = __ldg(p + hp*IMW + wp);
        float dx = (a02 - a00 + 2.f*(a12 - a10) + a22 - a20) * 0.125f;
        float dy = (a20 - a00 + 2.f*(a21 - a01) + a22 - a02) * 0.125f;
        msum += sqrtf(dx*dx + dy*dy + 1e-6f);
        asum += atan2f(dy, dx + 1e-6f);
    }
    float mag = msum * (1.f / CHN);
    float ang = asum * (1.f / CHN);
    ang = ang - PI_F * floorf(ang / PI_F);   // jnp % pi semantics
    const float binw = PI_F / NORI;
    const int pix = h * IMW + w;
#pragma unroll
    for (int o = 0; o < NORI; o++) {
        float cen = ((float)o + 0.5f) * binw;
        float wgt = 1.f - fabsf(ang - cen) / binw;
        wgt = wgt > 0.f ? wgt : 0.f;
        g_hogw[((long)b * NORI + o) * NPIX + pix] = wgt * mag;
    }
}

// ============================================================
// Depthwise 3x3 SAME (zero pad) on qkv; for v-channels (>=2C)
// fuse in hog projection: + sum_o W_hog[d,o]*hogw[b,o,pix].
// grid (IMW/32, IMH/8, BATCH*CH3), block (32,8).
// ============================================================
__global__ __launch_bounds__(256)
void dwconv_hog_kernel(const float* __restrict__ Wdw, const float* __restrict__ Whog)
{
    const int plane = blockIdx.z;        // b*CH3 + ch
    const int b  = plane / CH3;
    const int ch = plane - b * CH3;
    const int w  = blockIdx.x * 32 + threadIdx.x;
    const int h  = blockIdx.y * 8  + threadIdx.y;
    const float* in = g_qkv + (long)plane * NPIX;
    const float* kw = Wdw + ch * 9;
    float k0 = __ldg(kw+0), k1 = __ldg(kw+1), k2 = __ldg(kw+2);
    float k3 = __ldg(kw+3), k4 = __ldg(kw+4), k5 = __ldg(kw+5);
    float k6 = __ldg(kw+6), k7 = __ldg(kw+7), k8 = __ldg(kw+8);

    const int pix = h * IMW + w;
    const bool hm = h > 0, hp = h < IMH - 1, wm = w > 0, wp = w < IMW - 1;
    float v00 = (hm && wm) ? __ldg(in + pix - IMW - 1) : 0.f;
    float v01 =  hm        ? __ldg(in + pix - IMW    ) : 0.f;
    float v02 = (hm && wp) ? __ldg(in + pix - IMW + 1) : 0.f;
    float v10 =  wm        ? __ldg(in + pix       - 1) : 0.f;
    float v11 =              __ldg(in + pix          );
    float v12 =  wp        ? __ldg(in + pix       + 1) : 0.f;
    float v20 = (hp && wm) ? __ldg(in + pix + IMW - 1) : 0.f;
    float v21 =  hp        ? __ldg(in + pix + IMW    ) : 0.f;
    float v22 = (hp && wp) ? __ldg(in + pix + IMW + 1) : 0.f;

    float acc = k0*v00 + k1*v01 + k2*v02
              + k3*v10 + k4*v11 + k5*v12
              + k6*v20 + k7*v21 + k8*v22;

    if (ch >= 2 * CHN) {
        int d = ch - 2 * CHN;
        const float* hw = g_hogw + (long)b * NORI * NPIX + pix;
        float s = 0.f;
#pragma unroll
        for (int o = 0; o < NORI; o++)
            s += __ldg(Whog + d * NORI + o) * hw[(long)o * NPIX];
        acc += s;
    }
    g_qkvdw[(long)plane * NPIX + pix] = acc;
}

// ============================================================
// L2 norms of q (which=0) and k (which=1) rows over N=16384.
// grid 2*BATCH*CHN blocks, 256 threads.
// ============================================================
__global__ __launch_bounds__(256)
void norm_kernel()
{
    const int r = blockIdx.x;                // 0..3071
    const int which = r / (BATCH * CHN);
    const int rem = r - which * (BATCH * CHN);
    const int b = rem / CHN, ch = rem - b * CHN;
    const float* p = g_qkvdw + ((long)b * CH3 + which * CHN + ch) * NPIX;
    float s = 0.f;
    for (int i = threadIdx.x; i < NPIX; i += 256) { float v = p[i]; s += v * v; }
#pragma unroll
    for (int o = 16; o > 0; o >>= 1) s += __shfl_down_sync(0xffffffffu, s, o);
    __shared__ float sm[8];
    if ((threadIdx.x & 31) == 0) sm[threadIdx.x >> 5] = s;
    __syncthreads();
    if (threadIdx.x < 8) {
        float v = sm[threadIdx.x];
#pragma unroll
        for (int o = 4; o > 0; o >>= 1) v += __shfl_down_sync(0xffu, v, o);
        if (threadIdx.x == 0) g_norms[r] = sqrtf(v);
    }
}

// ============================================================
// attn partial: S[bh,split][c][d] = sum_{n in split} q[c,n]*k[d,n]
// grid (32, NSPLIT), 256 threads, 3x3 per-thread tile.
// ============================================================
__global__ __launch_bounds__(256)
void attn_partial_kernel()
{
    const int bh = blockIdx.x;
    const int split = blockIdx.y;
    const int b = bh >> 2, hh = bh & 3;
    const float* Q  = g_qkvdw + ((long)b * CH3 + hh * HDIM) * NPIX;
    const float* Kp = g_qkvdw + ((long)b * CH3 + CHN + hh * HDIM) * NPIX;
    __shared__ float Qs[32][HDIM + 1];
    __shared__ float Ks[32][HDIM + 1];
    const int t = threadIdx.x;
    const int ty = t >> 4, tx = t & 15;
    float acc[3][3];
#pragma unroll
    for (int i = 0; i < 3; i++)
#pragma unroll
        for (int j = 0; j < 3; j++) acc[i][j] = 0.f;

    const int nbase = split * SPLITLEN;
    for (int chunk = 0; chunk < SPLITLEN; chunk += 32) {
#pragma unroll
        for (int i = 0; i < 6; i++) {           // 6*256 = 32*48
            int e = t + i * 256;
            int c = e >> 5, kk = e & 31;
            Qs[kk][c] = Q [(long)c * NPIX + nbase + chunk + kk];
            Ks[kk][c] = Kp[(long)c * NPIX + nbase + chunk + kk];
        }
        __syncthreads();
#pragma unroll
        for (int kk = 0; kk < 32; kk++) {
            float q0 = Qs[kk][ty*3+0], q1 = Qs[kk][ty*3+1], q2 = Qs[kk][ty*3+2];
            float c0 = Ks[kk][tx*3+0], c1 = Ks[kk][tx*3+1], c2 = Ks[kk][tx*3+2];
            acc[0][0] += q0*c0; acc[0][1] += q0*c1; acc[0][2] += q0*c2;
            acc[1][0] += q1*c0; acc[1][1] += q1*c1; acc[1][2] += q1*c2;
            acc[2][0] += q2*c0; acc[2][1] += q2*c1; acc[2][2] += q2*c2;
        }
        __syncthreads();
    }
    float* dst = g_attnp + ((long)bh * NSPLIT + split) * HDIM * HDIM;
#pragma unroll
    for (int i = 0; i < 3; i++)
#pragma unroll
        for (int j = 0; j < 3; j++)
            dst[(ty*3 + i) * HDIM + tx*3 + j] = acc[i][j];
}

// ============================================================
// reduce splits + normalize by ||q||*||k|| * temperature + softmax(row)
// grid 32*48 blocks (one row), 64 threads.
// ============================================================
__global__ __launch_bounds__(64)
void softmax_kernel(const float* __restrict__ temp)
{
    const int blk = blockIdx.x;
    const int c  = blk % HDIM;
    const int bh = blk / HDIM;
    const int b = bh >> 2, hh = bh & 3;
    const int d = threadIdx.x;
    __shared__ float red[64];
    float val = -1e30f;
    if (d < HDIM) {
        const float* p = g_attnp + (long)bh * NSPLIT * HDIM * HDIM + c * HDIM + d;
        float s = 0.f;
#pragma unroll
        for (int sp = 0; sp < NSPLIT; sp++) s += p[(long)sp * HDIM * HDIM];
        float nq = g_norms[b * CHN + hh * HDIM + c];
        float nk = g_norms[BATCH * CHN + b * CHN + hh * HDIM + d];
        val = s / (fmaxf(nq, 1e-12f) * fmaxf(nk, 1e-12f)) * __ldg(temp + hh);
    }
    red[d] = val; __syncthreads();
    for (int o = 32; o > 0; o >>= 1) { if (d < o) red[d] = fmaxf(red[d], red[d + o]); __syncthreads(); }
    float mx = red[0]; __syncthreads();
    float e = (d < HDIM) ? expf(val - mx) : 0.f;
    red[d] = e; __syncthreads();
    for (int o = 32; o > 0; o >>= 1) { if (d < o) red[d] += red[d + o]; __syncthreads(); }
    if (d < HDIM)
        g_attn[(long)bh * HDIM * HDIM + c * HDIM + d] = e / red[0];
}

// ============================================================
// Fold W_proj with block-diagonal attn:
// Wf[b][e][h*48+d] = sum_c W_proj[e, h*48+c] * attn[b,h,c,d]
// grid (BATCH, NHEADS), 256 threads.
// ============================================================
__global__ __launch_bounds__(256)
void wf_kernel(const float* __restrict__ Wproj)
{
    const int b = blockIdx.x, hh = blockIdx.y;
    __shared__ float at[HDIM][HDIM];
    const int t = threadIdx.x;
    for (int i = t; i < HDIM * HDIM; i += 256)
        at[i / HDIM][i % HDIM] = g_attn[(long)(b * NHEADS + hh) * HDIM * HDIM + i];
    __syncthreads();
    for (int i = t; i < CHN * HDIM; i += 256) {
        int e = i / HDIM, d = i - e * HDIM;
        const float* wp = Wproj + (long)e * CHN + hh * HDIM;
        float acc = 0.f;
#pragma unroll
        for (int c2 = 0; c2 < HDIM; c2++) acc += __ldg(wp + c2) * at[c2][d];
        g_wf[((long)b * CHN + e) * CHN + hh * HDIM + d] = acc;
    }
}

// ============================================================
extern "C" void kernel_launch(void* const* d_in, const int* in_sizes, int n_in,
                              void* d_out, int out_size)
{
    const float* x     = (const float*)d_in[0];
    const float* Wqkv  = (const float*)d_in[1];
    const float* Wdw   = (const float*)d_in[2];
    const float* Whog  = (const float*)d_in[3];
    const float* Wproj = (const float*)d_in[4];
    const float* temp  = (const float*)d_in[5];
    float* out = (float*)d_out;

    void *p_qkv, *p_qkvdw, *p_wf;
    cudaGetSymbolAddress(&p_qkv,   g_qkv);
    cudaGetSymbolAddress(&p_qkvdw, g_qkvdw);
    cudaGetSymbolAddress(&p_wf,    g_wf);

    // 1) qkv = W_qkv @ x     (M=576, K=192, N=16384 per batch)
    gemm_kernel<<<dim3(NPIX / 128, CH3 / 64, BATCH), 256>>>(
        Wqkv, 0L,
        x, (long)CHN * NPIX,
        (float*)p_qkv, (long)CH3 * NPIX,
        NPIX, CHN);

    // 2) Sobel + HOG bin weights
    sobel_hog_kernel<<<dim3(IMH, BATCH), 128>>>(x);

    // 3) depthwise 3x3 (+hog add on v channels)
    dwconv_hog_kernel<<<dim3(IMW / 32, IMH / 8, BATCH * CH3), dim3(32, 8)>>>(Wdw, Whog);

    // 4) q,k row norms
    norm_kernel<<<2 * BATCH * CHN, 256>>>();

    // 5) q.k^T partial dots (split-K)
    attn_partial_kernel<<<dim3(BATCH * NHEADS, NSPLIT), 256>>>();

    // 6) reduce + scale + softmax
    softmax_kernel<<<BATCH * NHEADS * HDIM, 64>>>(temp);

    // 7) fold W_proj with attn -> per-batch 192x192
    wf_kernel<<<dim3(BATCH, NHEADS), 256>>>(Wproj);

    // 8) out = Wf @ v         (M=192, K=192, N=16384 per batch)
    gemm_kernel<<<dim3(NPIX / 128, CHN / 64, BATCH), 256>>>(
        (const float*)p_wf, (long)CHN * CHN,
        (const float*)p_qkvdw + (long)2 * CHN * NPIX, (long)CH3 * NPIX,
        out, (long)CHN * NPIX,
        NPIX, CHN);
}

// round 2
// speedup vs baseline: 2.1597x; 2.1597x over previous
#include <cuda_runtime.h>
#include <math.h>

#define BATCH 8
#define CHN 192
#define CH3 576
#define IMH 128
#define IMW 128
#define NPIX (IMH*IMW)         // 16384
#define NHEADS 4
#define HDIM 48
#define NORI 9
#define NSPLIT 32
#define SPLITLEN (NPIX/NSPLIT) // 512
#define PI_F 3.14159265358979323846f

// ---- device scratch (no allocation allowed) ----
__device__ float g_qkv  [BATCH*CH3*NPIX];
__device__ float g_qkvdw[BATCH*CH3*NPIX];
__device__ float g_hogw [BATCH*NORI*NPIX];
__device__ float g_norms[2*BATCH*CHN];
__device__ float g_attnp[BATCH*NHEADS*NSPLIT*HDIM*HDIM];
__device__ float g_attn [BATCH*NHEADS*HDIM*HDIM];
__device__ float g_wf   [BATCH*CHN*CHN];

__device__ __forceinline__ unsigned f2tf32(float x) {
    unsigned r;
    asm("cvt.rna.tf32.f32 %0, %1;" : "=r"(r) : "f"(x));
    return r;
}

// ============================================================
// tf32 tensor-core GEMM: C[z] (MxN) = A[z](MxK, lda=K) * B[z](KxN, ldb=N)
// BM=64 BN=128 BK=16, 256 thr (8 warps, 2x4), warp tile 32x32,
// mma.sync.m16n8k8 tf32, double-buffered smem, cvt.rna on smem store.
// Requires M%64==0, N%128==0, K%16==0.
// ============================================================
__global__ __launch_bounds__(256)
void gemm_tf32_kernel(const float* __restrict__ A, long sA,
                      const float* __restrict__ B, long sB,
                      float* __restrict__ Cm, long sC,
                      int N, int K)
{
    __shared__ unsigned As[2][16][68];    // [k][m], pad 4
    __shared__ unsigned Bs[2][16][132];   // [k][n], pad 4

    const int t = threadIdx.x;
    const int lane = t & 31;
    const int warp = t >> 5;
    const int wm = warp >> 2;        // 0..1
    const int wn = warp & 3;         // 0..3
    const int m0 = blockIdx.y * 64;
    const int n0 = blockIdx.x * 128;
    const float* Ab = A + (long)blockIdx.z * sA;
    const float* Bb = B + (long)blockIdx.z * sB;
    float*       Cb = Cm + (long)blockIdx.z * sC;

    const int arow = t >> 2;          // 0..63
    const int ac4  = t & 3;           // float4 idx in row (k/4)
    const int brow0 = t >> 5;         // 0..7
    const int bc4   = t & 31;         // 0..31

    float acc[2][4][4];
#pragma unroll
    for (int i = 0; i < 2; i++)
#pragma unroll
        for (int j = 0; j < 4; j++)
#pragma unroll
            for (int r = 0; r < 4; r++) acc[i][j][r] = 0.f;

    const int niter = K / 16;

    // preload iter 0 into buf 0
    {
        float4 va = *(const float4*)(Ab + (long)(m0 + arow) * K + ac4 * 4);
        As[0][ac4*4+0][arow] = f2tf32(va.x);
        As[0][ac4*4+1][arow] = f2tf32(va.y);
        As[0][ac4*4+2][arow] = f2tf32(va.z);
        As[0][ac4*4+3][arow] = f2tf32(va.w);
        float4 vb0 = *(const float4*)(Bb + (long)brow0 * N + n0 + bc4 * 4);
        float4 vb1 = *(const float4*)(Bb + (long)(brow0 + 8) * N + n0 + bc4 * 4);
        Bs[0][brow0][bc4*4+0] = f2tf32(vb0.x); Bs[0][brow0][bc4*4+1] = f2tf32(vb0.y);
        Bs[0][brow0][bc4*4+2] = f2tf32(vb0.z); Bs[0][brow0][bc4*4+3] = f2tf32(vb0.w);
        Bs[0][brow0+8][bc4*4+0] = f2tf32(vb1.x); Bs[0][brow0+8][bc4*4+1] = f2tf32(vb1.y);
        Bs[0][brow0+8][bc4*4+2] = f2tf32(vb1.z); Bs[0][brow0+8][bc4*4+3] = f2tf32(vb1.w);
    }
    __syncthreads();

    int cur = 0;
    for (int it = 0; it < niter; it++) {
        float4 va_n, vb0_n, vb1_n;
        const bool more = (it + 1) < niter;
        if (more) {
            int k0 = (it + 1) * 16;
            va_n  = *(const float4*)(Ab + (long)(m0 + arow) * K + k0 + ac4 * 4);
            vb0_n = *(const float4*)(Bb + (long)(k0 + brow0) * N + n0 + bc4 * 4);
            vb1_n = *(const float4*)(Bb + (long)(k0 + brow0 + 8) * N + n0 + bc4 * 4);
        }

#pragma unroll
        for (int kk = 0; kk < 2; kk++) {
            const int kb = kk * 8;
            unsigned af[2][4], bf[4][2];
#pragma unroll
            for (int mt = 0; mt < 2; mt++) {
                int r = wm * 32 + mt * 16 + (lane >> 2);
                af[mt][0] = As[cur][kb + (lane & 3)    ][r];
                af[mt][1] = As[cur][kb + (lane & 3)    ][r + 8];
                af[mt][2] = As[cur][kb + (lane & 3) + 4][r];
                af[mt][3] = As[cur][kb + (lane & 3) + 4][r + 8];
            }
#pragma unroll
            for (int nt = 0; nt < 4; nt++) {
                int c = wn * 32 + nt * 8 + (lane >> 2);
                bf[nt][0] = Bs[cur][kb + (lane & 3)    ][c];
                bf[nt][1] = Bs[cur][kb + (lane & 3) + 4][c];
            }
#pragma unroll
            for (int mt = 0; mt < 2; mt++)
#pragma unroll
                for (int nt = 0; nt < 4; nt++) {
                    asm volatile(
                        "mma.sync.aligned.m16n8k8.row.col.f32.tf32.tf32.f32 "
                        "{%0,%1,%2,%3}, {%4,%5,%6,%7}, {%8,%9}, {%0,%1,%2,%3};\n"
                        : "+f"(acc[mt][nt][0]), "+f"(acc[mt][nt][1]),
                          "+f"(acc[mt][nt][2]), "+f"(acc[mt][nt][3])
                        : "r"(af[mt][0]), "r"(af[mt][1]), "r"(af[mt][2]), "r"(af[mt][3]),
                          "r"(bf[nt][0]), "r"(bf[nt][1]));
                }
        }

        if (more) {
            int nxt = cur ^ 1;
            As[nxt][ac4*4+0][arow] = f2tf32(va_n.x);
            As[nxt][ac4*4+1][arow] = f2tf32(va_n.y);
            As[nxt][ac4*4+2][arow] = f2tf32(va_n.z);
            As[nxt][ac4*4+3][arow] = f2tf32(va_n.w);
            Bs[nxt][brow0][bc4*4+0] = f2tf32(vb0_n.x); Bs[nxt][brow0][bc4*4+1] = f2tf32(vb0_n.y);
            Bs[nxt][brow0][bc4*4+2] = f2tf32(vb0_n.z); Bs[nxt][brow0][bc4*4+3] = f2tf32(vb0_n.w);
            Bs[nxt][brow0+8][bc4*4+0] = f2tf32(vb1_n.x); Bs[nxt][brow0+8][bc4*4+1] = f2tf32(vb1_n.y);
            Bs[nxt][brow0+8][bc4*4+2] = f2tf32(vb1_n.z); Bs[nxt][brow0+8][bc4*4+3] = f2tf32(vb1_n.w);
            __syncthreads();
            cur = nxt;
        }
    }

    // epilogue
#pragma unroll
    for (int mt = 0; mt < 2; mt++) {
        int r = m0 + wm * 32 + mt * 16 + (lane >> 2);
#pragma unroll
        for (int nt = 0; nt < 4; nt++) {
            int c = n0 + wn * 32 + nt * 8 + (lane & 3) * 2;
            float2 lo = make_float2(acc[mt][nt][0], acc[mt][nt][1]);
            float2 hi = make_float2(acc[mt][nt][2], acc[mt][nt][3]);
            *(float2*)(Cb + (long)r * N + c)       = lo;
            *(float2*)(Cb + (long)(r + 8) * N + c) = hi;
        }
    }
}

// ============================================================
// Sobel (replicate pad, /8 kernels) -> channel-mean mag/ang -> HOG weights
// ============================================================
__global__ __launch_bounds__(128)
void sobel_hog_kernel(const float* __restrict__ x)
{
    const int w = threadIdx.x;
    const int h = blockIdx.x;
    const int b = blockIdx.y;
    const int hm = h > 0 ? h - 1 : 0;
    const int hp = h < IMH - 1 ? h + 1 : IMH - 1;
    const int wm = w > 0 ? w - 1 : 0;
    const int wp = w < IMW - 1 ? w + 1 : IMW - 1;
    const float* xb = x + (long)b * CHN * NPIX;

    float msum = 0.f, asum = 0.f;
    for (int c = 0; c < CHN; c++) {
        const float* p = xb + (long)c * NPIX;
        float a00 = __ldg(p + hm*IMW + wm), a01 = __ldg(p + hm*IMW + w), a02 = __ldg(p + hm*IMW + wp);
        float a10 = __ldg(p + h *IMW + wm),                              a12 = __ldg(p + h *IMW + wp);
        float a20 = __ldg(p + hp*IMW + wm), a21 = __ldg(p + hp*IMW + w), a22 = __ldg(p + hp*IMW + wp);
        float dx = (a02 - a00 + 2.f*(a12 - a10) + a22 - a20) * 0.125f;
        float dy = (a20 - a00 + 2.f*(a21 - a01) + a22 - a02) * 0.125f;
        msum += sqrtf(dx*dx + dy*dy + 1e-6f);
        asum += atan2f(dy, dx + 1e-6f);
    }
    float mag = msum * (1.f / CHN);
    float ang = asum * (1.f / CHN);
    ang = ang - PI_F * floorf(ang / PI_F);
    const float binw = PI_F / NORI;
    const int pix = h * IMW + w;
#pragma unroll
    for (int o = 0; o < NORI; o++) {
        float cen = ((float)o + 0.5f) * binw;
        float wgt = 1.f - fabsf(ang - cen) / binw;
        wgt = wgt > 0.f ? wgt : 0.f;
        g_hogw[((long)b * NORI + o) * NPIX + pix] = wgt * mag;
    }
}

// ============================================================
// Depthwise 3x3 SAME (zero pad), 4 pixels per thread, fused HOG add on v.
// grid (1, IMH/8, BATCH*CH3), block (32,8).
// ============================================================
__global__ __launch_bounds__(256)
void dwconv_hog_kernel(const float* __restrict__ Wdw, const float* __restrict__ Whog)
{
    const int plane = blockIdx.z;
    const int b  = plane / CH3;
    const int ch = plane - b * CH3;
    const int w0 = threadIdx.x * 4;
    const int h  = blockIdx.y * 8 + threadIdx.y;
    const float* in = g_qkv + (long)plane * NPIX;
    const float* kw = Wdw + ch * 9;
    float k0 = __ldg(kw+0), k1 = __ldg(kw+1), k2 = __ldg(kw+2);
    float k3 = __ldg(kw+3), k4 = __ldg(kw+4), k5 = __ldg(kw+5);
    float k6 = __ldg(kw+6), k7 = __ldg(kw+7), k8 = __ldg(kw+8);

    float row[3][6];
#pragma unroll
    for (int rr = 0; rr < 3; rr++) {
        int hh = h + rr - 1;
        if (hh >= 0 && hh < IMH) {
            const float* p = in + hh * IMW + w0;
            float4 cv = *(const float4*)p;
            row[rr][1] = cv.x; row[rr][2] = cv.y; row[rr][3] = cv.z; row[rr][4] = cv.w;
            row[rr][0] = (w0 > 0)       ? __ldg(p - 1) : 0.f;
            row[rr][5] = (w0 + 4 < IMW) ? __ldg(p + 4) : 0.f;
        } else {
#pragma unroll
            for (int j = 0; j < 6; j++) row[rr][j] = 0.f;
        }
    }

    float out[4];
#pragma unroll
    for (int j = 0; j < 4; j++) {
        out[j] = k0*row[0][j] + k1*row[0][j+1] + k2*row[0][j+2]
               + k3*row[1][j] + k4*row[1][j+1] + k5*row[1][j+2]
               + k6*row[2][j] + k7*row[2][j+1] + k8*row[2][j+2];
    }

    const int pix = h * IMW + w0;
    if (ch >= 2 * CHN) {
        int d = ch - 2 * CHN;
        const float* hw = g_hogw + (long)b * NORI * NPIX + pix;
#pragma unroll
        for (int o = 0; o < NORI; o++) {
            float wgt = __ldg(Whog + d * NORI + o);
            float4 hv = *(const float4*)(hw + (long)o * NPIX);
            out[0] += wgt * hv.x; out[1] += wgt * hv.y;
            out[2] += wgt * hv.z; out[3] += wgt * hv.w;
        }
    }
    *(float4*)(g_qkvdw + (long)plane * NPIX + pix) =
        make_float4(out[0], out[1], out[2], out[3]);
}

// ============================================================
// L2 norms of q/k rows over N=16384.
// ============================================================
__global__ __launch_bounds__(256)
void norm_kernel()
{
    const int r = blockIdx.x;
    const int which = r / (BATCH * CHN);
    const int rem = r - which * (BATCH * CHN);
    const int b = rem / CHN, ch = rem - b * CHN;
    const float* p = g_qkvdw + ((long)b * CH3 + which * CHN + ch) * NPIX;
    float s = 0.f;
    for (int i = threadIdx.x; i < NPIX / 4; i += 256) {
        float4 v = *(const float4*)(p + i * 4);
        s += v.x*v.x + v.y*v.y + v.z*v.z + v.w*v.w;
    }
#pragma unroll
    for (int o = 16; o > 0; o >>= 1) s += __shfl_down_sync(0xffffffffu, s, o);
    __shared__ float sm[8];
    if ((threadIdx.x & 31) == 0) sm[threadIdx.x >> 5] = s;
    __syncthreads();
    if (threadIdx.x < 8) {
        float v = sm[threadIdx.x];
#pragma unroll
        for (int o = 4; o > 0; o >>= 1) v += __shfl_down_sync(0xffu, v, o);
        if (threadIdx.x == 0) g_norms[r] = sqrtf(v);
    }
}

// ============================================================
// attn partial: S[bh,split][c][d] = sum_{n in split} q[c,n]*k[d,n]
// ============================================================
__global__ __launch_bounds__(256)
void attn_partial_kernel()
{
    const int bh = blockIdx.x;
    const int split = blockIdx.y;
    const int b = bh >> 2, hh = bh & 3;
    const float* Q  = g_qkvdw + ((long)b * CH3 + hh * HDIM) * NPIX;
    const float* Kp = g_qkvdw + ((long)b * CH3 + CHN + hh * HDIM) * NPIX;
    __shared__ float Qs[32][HDIM + 1];
    __shared__ float Ks[32][HDIM + 1];
    const int t = threadIdx.x;
    const int ty = t >> 4, tx = t & 15;
    float acc[3][3];
#pragma unroll
    for (int i = 0; i < 3; i++)
#pragma unroll
        for (int j = 0; j < 3; j++) acc[i][j] = 0.f;

    const int nbase = split * SPLITLEN;
    for (int chunk = 0; chunk < SPLITLEN; chunk += 32) {
#pragma unroll
        for (int i = 0; i < 6; i++) {
            int e = t + i * 256;
            int c = e >> 5, kk = e & 31;
            Qs[kk][c] = Q [(long)c * NPIX + nbase + chunk + kk];
            Ks[kk][c] = Kp[(long)c * NPIX + nbase + chunk + kk];
        }
        __syncthreads();
#pragma unroll
        for (int kk = 0; kk < 32; kk++) {
            float q0 = Qs[kk][ty*3+0], q1 = Qs[kk][ty*3+1], q2 = Qs[kk][ty*3+2];
            float c0 = Ks[kk][tx*3+0], c1 = Ks[kk][tx*3+1], c2 = Ks[kk][tx*3+2];
            acc[0][0] += q0*c0; acc[0][1] += q0*c1; acc[0][2] += q0*c2;
            acc[1][0] += q1*c0; acc[1][1] += q1*c1; acc[1][2] += q1*c2;
            acc[2][0] += q2*c0; acc[2][1] += q2*c1; acc[2][2] += q2*c2;
        }
        __syncthreads();
    }
    float* dst = g_attnp + ((long)bh * NSPLIT + split) * HDIM * HDIM;
#pragma unroll
    for (int i = 0; i < 3; i++)
#pragma unroll
        for (int j = 0; j < 3; j++)
            dst[(ty*3 + i) * HDIM + tx*3 + j] = acc[i][j];
}

// ============================================================
// reduce splits + normalize + softmax
// ============================================================
__global__ __launch_bounds__(64)
void softmax_kernel(const float* __restrict__ temp)
{
    const int blk = blockIdx.x;
    const int c  = blk % HDIM;
    const int bh = blk / HDIM;
    const int b = bh >> 2, hh = bh & 3;
    const int d = threadIdx.x;
    __shared__ float red[64];
    float val = -1e30f;
    if (d < HDIM) {
        const float* p = g_attnp + (long)bh * NSPLIT * HDIM * HDIM + c * HDIM + d;
        float s = 0.f;
#pragma unroll
        for (int sp = 0; sp < NSPLIT; sp++) s += p[(long)sp * HDIM * HDIM];
        float nq = g_norms[b * CHN + hh * HDIM + c];
        float nk = g_norms[BATCH * CHN + b * CHN + hh * HDIM + d];
        val = s / (fmaxf(nq, 1e-12f) * fmaxf(nk, 1e-12f)) * __ldg(temp + hh);
    }
    red[d] = val; __syncthreads();
    for (int o = 32; o > 0; o >>= 1) { if (d < o) red[d] = fmaxf(red[d], red[d + o]); __syncthreads(); }
    float mx = red[0]; __syncthreads();
    float e = (d < HDIM) ? expf(val - mx) : 0.f;
    red[d] = e; __syncthreads();
    for (int o = 32; o > 0; o >>= 1) { if (d < o) red[d] += red[d + o]; __syncthreads(); }
    if (d < HDIM)
        g_attn[(long)bh * HDIM * HDIM + c * HDIM + d] = e / red[0];
}

// ============================================================
// Fold W_proj with block-diagonal attn
// ============================================================
__global__ __launch_bounds__(256)
void wf_kernel(const float* __restrict__ Wproj)
{
    const int b = blockIdx.x, hh = blockIdx.y;
    __shared__ float at[HDIM][HDIM];
    const int t = threadIdx.x;
    for (int i = t; i < HDIM * HDIM; i += 256)
        at[i / HDIM][i % HDIM] = g_attn[(long)(b * NHEADS + hh) * HDIM * HDIM + i];
    __syncthreads();
    for (int i = t; i < CHN * HDIM; i += 256) {
        int e = i / HDIM, d = i - e * HDIM;
        const float* wp = Wproj + (long)e * CHN + hh * HDIM;
        float acc = 0.f;
#pragma unroll
        for (int c2 = 0; c2 < HDIM; c2++) acc += __ldg(wp + c2) * at[c2][d];
        g_wf[((long)b * CHN + e) * CHN + hh * HDIM + d] = acc;
    }
}

// ============================================================
extern "C" void kernel_launch(void* const* d_in, const int* in_sizes, int n_in,
                              void* d_out, int out_size)
{
    const float* x     = (const float*)d_in[0];
    const float* Wqkv  = (const float*)d_in[1];
    const float* Wdw   = (const float*)d_in[2];
    const float* Whog  = (const float*)d_in[3];
    const float* Wproj = (const float*)d_in[4];
    const float* temp  = (const float*)d_in[5];
    float* out = (float*)d_out;

    void *p_qkv, *p_qkvdw, *p_wf;
    cudaGetSymbolAddress(&p_qkv,   g_qkv);
    cudaGetSymbolAddress(&p_qkvdw, g_qkvdw);
    cudaGetSymbolAddress(&p_wf,    g_wf);

    // 1) qkv = W_qkv @ x     (M=576, K=192, N=16384 per batch) — tf32 MMA
    gemm_tf32_kernel<<<dim3(NPIX / 128, CH3 / 64, BATCH), 256>>>(
        Wqkv, 0L,
        x, (long)CHN * NPIX,
        (float*)p_qkv, (long)CH3 * NPIX,
        NPIX, CHN);

    // 2) Sobel + HOG bin weights
    sobel_hog_kernel<<<dim3(IMH, BATCH), 128>>>(x);

    // 3) depthwise 3x3 (+hog add on v channels), 4 px/thread
    dwconv_hog_kernel<<<dim3(1, IMH / 8, BATCH * CH3), dim3(32, 8)>>>(Wdw, Whog);

    // 4) q,k row norms
    norm_kernel<<<2 * BATCH * CHN, 256>>>();

    // 5) q.k^T partial dots (split-K)
    attn_partial_kernel<<<dim3(BATCH * NHEADS, NSPLIT), 256>>>();

    // 6) reduce + scale + softmax
    softmax_kernel<<<BATCH * NHEADS * HDIM, 64>>>(temp);

    // 7) fold W_proj with attn -> per-batch 192x192
    wf_kernel<<<dim3(BATCH, NHEADS), 256>>>(Wproj);

    // 8) out = Wf @ v         (M=192, K=192, N=16384 per batch) — tf32 MMA
    gemm_tf32_kernel<<<dim3(NPIX / 128, CHN / 64, BATCH), 256>>>(
        (const float*)p_wf, (long)CHN * CHN,
        (const float*)p_qkvdw + (long)2 * CHN * NPIX, (long)CH3 * NPIX,
        out, (long)CHN * NPIX,
        NPIX, CHN);
}